// round 1
// baseline (speedup 1.0000x reference)
#include <cuda_runtime.h>
#include <cstdint>

// Problem shape (fixed by the dataset)
#define EXPERTS 16
#define MTOK    2048
#define DIM     1024
#define HID     4096

// 512 MB scratch for the hidden activations (allocation-free rule: __device__ global)
__device__ float g_hidden[(size_t)EXPERTS * MTOK * HID];

// Tiling
#define BM 128
#define BN 128
#define BK 16
#define A_STRIDE (BK + 4)    // 20 words: bank = (20m+k)%32 -> conflict-free frag loads
#define B_STRIDE (BN + 8)    // 136 words: bank = (8k+n)%32 -> conflict-free frag loads

__device__ __forceinline__ unsigned cvt_tf32(float x) {
    unsigned u;
    asm("cvt.rna.tf32.f32 %0, %1;" : "=r"(u) : "f"(x));
    return u;
}

__device__ __forceinline__ void cp_async16(void* smem, const void* gmem) {
    unsigned s = (unsigned)__cvta_generic_to_shared(smem);
    asm volatile("cp.async.cg.shared.global [%0], [%1], 16;\n" :: "r"(s), "l"(gmem));
}

__device__ __forceinline__ float gelu_exact(float x) {
    // jax.nn.gelu(approximate=False): 0.5*x*(1+erf(x/sqrt(2)))
    return 0.5f * x * (1.0f + erff(x * 0.70710678118654752440f));
}

// C[M,N] = op(A[M,K] @ B[K,N] + bias[N]);  A,B,C row-major, per-expert via blockIdx.z
template <bool GELU>
__global__ void __launch_bounds__(256, 2)
gemm_tf32(const float* __restrict__ A, const float* __restrict__ B,
          const float* __restrict__ bias, float* __restrict__ C,
          int M, int N, int K)
{
    __shared__ float As[2][BM][A_STRIDE];
    __shared__ float Bs[2][BK][B_STRIDE];

    const int e = blockIdx.z;
    A += (size_t)e * M * K;
    B += (size_t)e * K * N;
    C += (size_t)e * M * N;

    const int mBase = blockIdx.y * BM;
    const int nBase = blockIdx.x * BN;

    const int tid  = threadIdx.x;
    const int warp = tid >> 5;
    const int lane = tid & 31;
    const int g    = lane >> 2;   // group id (0..7)
    const int t    = lane & 3;    // thread-in-group (0..3)
    const int wm   = (warp & 3) * 32;   // 4 warps along M
    const int wn   = (warp >> 2) * 64;  // 2 warps along N

    float c[2][8][4];
    #pragma unroll
    for (int im = 0; im < 2; im++)
        #pragma unroll
        for (int in = 0; in < 8; in++)
            #pragma unroll
            for (int r = 0; r < 4; r++)
                c[im][in][r] = 0.0f;

    // --- tile loaders: 512 float4 per tile, 2 per thread ---
    auto loadA = [&](int s, int kBase) {
        #pragma unroll
        for (int i = 0; i < 2; i++) {
            int idx = tid + i * 256;
            int r = idx >> 2, c4 = idx & 3;           // 128 rows x 4 float4
            cp_async16(&As[s][r][c4 * 4],
                       &A[(size_t)(mBase + r) * K + kBase + c4 * 4]);
        }
    };
    auto loadB = [&](int s, int kBase) {
        #pragma unroll
        for (int i = 0; i < 2; i++) {
            int idx = tid + i * 256;
            int r = idx >> 5, c4 = idx & 31;          // 16 rows x 32 float4
            cp_async16(&Bs[s][r][c4 * 4],
                       &B[(size_t)(kBase + r) * N + nBase + c4 * 4]);
        }
    };

    const int KT = K / BK;

    loadA(0, 0);
    loadB(0, 0);
    asm volatile("cp.async.commit_group;\n");

    for (int kt = 0; kt < KT; kt++) {
        asm volatile("cp.async.wait_group 0;\n");
        __syncthreads();

        if (kt + 1 < KT) {
            loadA((kt + 1) & 1, (kt + 1) * BK);
            loadB((kt + 1) & 1, (kt + 1) * BK);
            asm volatile("cp.async.commit_group;\n");
        }

        const int s = kt & 1;
        #pragma unroll
        for (int ks = 0; ks < BK; ks += 8) {
            unsigned a[2][4], b[8][2];
            #pragma unroll
            for (int im = 0; im < 2; im++) {
                int m0 = wm + im * 16;
                a[im][0] = cvt_tf32(As[s][m0 + g][ks + t]);
                a[im][1] = cvt_tf32(As[s][m0 + g + 8][ks + t]);
                a[im][2] = cvt_tf32(As[s][m0 + g][ks + t + 4]);
                a[im][3] = cvt_tf32(As[s][m0 + g + 8][ks + t + 4]);
            }
            #pragma unroll
            for (int in = 0; in < 8; in++) {
                int n0 = wn + in * 8 + g;
                b[in][0] = cvt_tf32(Bs[s][ks + t][n0]);
                b[in][1] = cvt_tf32(Bs[s][ks + t + 4][n0]);
            }
            #pragma unroll
            for (int im = 0; im < 2; im++)
                #pragma unroll
                for (int in = 0; in < 8; in++) {
                    asm volatile(
                        "mma.sync.aligned.m16n8k8.row.col.f32.tf32.tf32.f32 "
                        "{%0,%1,%2,%3}, {%4,%5,%6,%7}, {%8,%9}, {%0,%1,%2,%3};"
                        : "+f"(c[im][in][0]), "+f"(c[im][in][1]),
                          "+f"(c[im][in][2]), "+f"(c[im][in][3])
                        : "r"(a[im][0]), "r"(a[im][1]), "r"(a[im][2]), "r"(a[im][3]),
                          "r"(b[in][0]), "r"(b[in][1]));
                }
        }
        __syncthreads();
    }

    // --- epilogue: bias (+ gelu), float2 stores ---
    #pragma unroll
    for (int im = 0; im < 2; im++) {
        #pragma unroll
        for (int rh = 0; rh < 2; rh++) {
            int row = mBase + wm + im * 16 + g + rh * 8;
            #pragma unroll
            for (int in = 0; in < 8; in++) {
                int col = nBase + wn + in * 8 + 2 * t;
                float v0 = c[im][in][rh * 2 + 0] + bias[col];
                float v1 = c[im][in][rh * 2 + 1] + bias[col + 1];
                if (GELU) { v0 = gelu_exact(v0); v1 = gelu_exact(v1); }
                *reinterpret_cast<float2*>(&C[(size_t)row * N + col]) =
                    make_float2(v0, v1);
            }
        }
    }
}

extern "C" void kernel_launch(void* const* d_in, const int* in_sizes, int n_in,
                              void* d_out, int out_size)
{
    const float* x  = (const float*)d_in[0];   // [E, N, D]
    const float* w1 = (const float*)d_in[1];   // [E, D, H]
    const float* w2 = (const float*)d_in[2];   // [E, H, D]
    const float* b1 = (const float*)d_in[3];   // [H]
    const float* b2 = (const float*)d_in[4];   // [D]
    float* out = (float*)d_out;                // [E, N, D]

    float* hidden = nullptr;
    cudaGetSymbolAddress((void**)&hidden, g_hidden);

    dim3 block(256);
    // GEMM1 + exact GELU: hidden[e] = gelu(x[e] @ w1[e] + b1)
    gemm_tf32<true><<<dim3(HID / BN, MTOK / BM, EXPERTS), block>>>(
        x, w1, b1, hidden, MTOK, HID, DIM);
    // GEMM2: out[e] = hidden[e] @ w2[e] + b2
    gemm_tf32<false><<<dim3(DIM / BN, MTOK / BM, EXPERTS), block>>>(
        hidden, w2, b2, out, MTOK, DIM, HID);
}

// round 5
// speedup vs baseline: 1.0502x; 1.0502x over previous
#include <cuda_runtime.h>
#include <cstdint>

// Problem shape (fixed)
#define EXPERTS 16
#define MTOK    2048
#define DIM     1024
#define HID     4096

// GEMM tiling
#define BM 128
#define BN 128
#define BK 32
#define ASTR 36                       // padded floats per A smem row (all-32-bank frag loads)
#define A_STG (BM*ASTR)               // 4608 floats
#define B_STG (BN*BK)                 // 4096 floats (16KB pair-packed swizzled panel)
#define STG   (A_STG + B_STG)         // 8704 floats
#define SMEM_BYTES (3*STG*4)          // 104448 B -> 2 CTAs/SM

// Scratch (allocation-free rule: __device__ globals)
__device__ float g_xp [(size_t)EXPERTS*MTOK*DIM];   // x, rna-rounded, plain row-major
__device__ float g_w1p[(size_t)EXPERTS*DIM*HID];    // w1^T panels [e][nb][kb][128n x 16 float2]
__device__ float g_w2p[(size_t)EXPERTS*HID*DIM];    // w2^T panels
__device__ float g_hid[(size_t)EXPERTS*MTOK*HID];   // hidden, rounded, plain row-major

// ---------------- helpers ----------------
__device__ __forceinline__ float cvt_rna_f(float x){
    unsigned u; asm("cvt.rna.tf32.f32 %0, %1;" : "=r"(u) : "f"(x)); return __uint_as_float(u);
}
__device__ __forceinline__ float gelu_exact(float x){
    return 0.5f*x*(1.0f+erff(x*0.70710678118654752440f));
}
__device__ __forceinline__ void cp16(void* smem, const void* gmem){
    unsigned s = (unsigned)__cvta_generic_to_shared(smem);
    asm volatile("cp.async.cg.shared.global [%0], [%1], 16;\n" :: "r"(s), "l"(gmem));
}

// ---------------- pre-pass: round x ----------------
__global__ __launch_bounds__(256) void convert_x(const float4* __restrict__ X, float4* __restrict__ P){
    const size_t total = (size_t)EXPERTS*MTOK*DIM/4;
    size_t stride = (size_t)gridDim.x*blockDim.x;
    for (size_t i = (size_t)blockIdx.x*blockDim.x + threadIdx.x; i < total; i += stride){
        float4 v = X[i];
        v.x=cvt_rna_f(v.x); v.y=cvt_rna_f(v.y); v.z=cvt_rna_f(v.z); v.w=cvt_rna_f(v.w);
        P[i] = v;
    }
}

// ---- pre-pass: W[K,N] -> rounded W^T pair-packed swizzled panels [e][nb][kb] ----
// Panel = 128 n-rows x 32 k, row = 16 float2 (pair j -> k = 8*(j/4)+(j%4), .y = +4),
// byte offset swizzled: off ^ ((off>>3)&0x70).
__global__ __launch_bounds__(256) void pack_w(const float* __restrict__ W, float* __restrict__ P,
                                              int K, int N){
    __shared__ float ts[32][133];
    const int e = blockIdx.z, nb = blockIdx.x, kb = blockIdx.y;
    const float* src = W + ((size_t)e*K + (size_t)kb*32)*N + (size_t)nb*128;
    #pragma unroll
    for (int i=0;i<16;i++){
        int idx = threadIdx.x + i*256;
        int r = idx>>7, c = idx&127;
        ts[r][c] = src[(size_t)r*N + c];
    }
    __syncthreads();
    char* panel = (char*)(P + (((size_t)e*(N>>7) + nb)*(size_t)(K>>5) + kb)*(size_t)B_STG);
    #pragma unroll
    for (int i=0;i<8;i++){
        int idx = threadIdx.x + i*256;
        int n = idx>>4, j = idx&15;
        int k0 = ((j>>2)<<3) + (j&3);
        float2 v = make_float2(cvt_rna_f(ts[k0][n]), cvt_rna_f(ts[k0+4][n]));
        uint32_t off = (uint32_t)(n*128 + j*8);
        off ^= (off>>3)&0x70;
        *(float2*)(panel + off) = v;
    }
}

// ---------------- main GEMM: mma.sync tf32, cvt-free mainloop ----------------
// A[M,K] row-major (pre-rounded), B = pair-packed swizzled [N,K] panels.
template<bool G1>
__global__ void __launch_bounds__(256,2)
gemm_t(const float* __restrict__ A, const float* __restrict__ Bp,
       const float* __restrict__ bias, float* __restrict__ Out, int K)
{
    extern __shared__ float sm[];
    const int tid = threadIdx.x, warp = tid>>5, lane = tid&31;
    const int g = lane>>2, t = lane&3;
    const int wm = (warp&3)*32, wn = (warp>>2)*64;
    const int bx = blockIdx.x, by = blockIdx.y, e = blockIdx.z;
    const int NB = gridDim.x;
    const int KT = K/BK;

    const float* Ae = A  + ((size_t)e*MTOK + (size_t)by*BM)*K;
    const float* Bb = Bp + ((size_t)e*NB + bx)*(size_t)KT*B_STG;

    auto loadA = [&](int slot, int kb){
        float* dst = sm + slot*STG;
        const float* src = Ae + kb*BK;
        #pragma unroll
        for (int j=0;j<4;j++){
            int idx = tid + j*256;
            int r = idx>>3, c4 = idx&7;
            cp16(dst + r*ASTR + c4*4, src + (size_t)r*K + c4*4);
        }
    };
    auto loadB = [&](int slot, int kb){
        float* dst = sm + slot*STG + A_STG;
        const float* src = Bb + (size_t)kb*B_STG;
        #pragma unroll
        for (int j=0;j<4;j++){
            int idx = tid + j*256;
            cp16(dst + idx*4, src + idx*4);
        }
    };

    float c[2][8][4];
    #pragma unroll
    for (int im=0;im<2;im++)
        #pragma unroll
        for (int in=0;in<8;in++)
            #pragma unroll
            for (int r=0;r<4;r++) c[im][in][r]=0.0f;

    loadA(0,0); loadB(0,0); asm volatile("cp.async.commit_group;\n");
    loadA(1,1); loadB(1,1); asm volatile("cp.async.commit_group;\n");

    for (int s=0; s<KT; s++){
        asm volatile("cp.async.wait_group 1;\n");
        __syncthreads();
        if (s+2 < KT){ int ns=(s+2)%3; loadA(ns,s+2); loadB(ns,s+2); }
        asm volatile("cp.async.commit_group;\n");   // always commit -> exact group accounting

        const uint32_t* Au = (const uint32_t*)(sm + (s%3)*STG);
        const char*     Bc = (const char*)   (sm + (s%3)*STG + A_STG);
        #pragma unroll
        for (int ck=0; ck<4; ck++){
            uint32_t a[2][4];
            #pragma unroll
            for (int im=0;im<2;im++){
                int r0 = (wm + im*16 + g)*ASTR + ck*8 + t;
                a[im][0] = Au[r0];
                a[im][1] = Au[r0 + 8*ASTR];
                a[im][2] = Au[r0 + 4];
                a[im][3] = Au[r0 + 8*ASTR + 4];
            }
            uint32_t b[8][2];
            #pragma unroll
            for (int in=0;in<8;in++){
                int n0 = wn + in*8 + g;
                uint32_t off = (uint32_t)(n0*128) + (uint32_t)(((ck*32 + t*8)) ^ (g*16));
                float2 v = *(const float2*)(Bc + off);
                b[in][0] = __float_as_uint(v.x);
                b[in][1] = __float_as_uint(v.y);
            }
            #pragma unroll
            for (int im=0;im<2;im++)
                #pragma unroll
                for (int in=0;in<8;in++){
                    asm volatile(
                        "mma.sync.aligned.m16n8k8.row.col.f32.tf32.tf32.f32 "
                        "{%0,%1,%2,%3}, {%4,%5,%6,%7}, {%8,%9}, {%0,%1,%2,%3};"
                        : "+f"(c[im][in][0]), "+f"(c[im][in][1]),
                          "+f"(c[im][in][2]), "+f"(c[im][in][3])
                        : "r"(a[im][0]), "r"(a[im][1]), "r"(a[im][2]), "r"(a[im][3]),
                          "r"(b[in][0]), "r"(b[in][1]));
                }
        }
    }
    asm volatile("cp.async.wait_group 0;\n");

    // ---- epilogue ----
    const int Nout = NB*BN;
    #pragma unroll
    for (int im=0;im<2;im++){
        #pragma unroll
        for (int rh=0;rh<2;rh++){
            int row = by*BM + wm + im*16 + g + rh*8;
            #pragma unroll
            for (int in=0;in<8;in++){
                int col = bx*BN + wn + in*8 + 2*t;
                float v0 = c[im][in][rh*2+0] + __ldg(&bias[col]);
                float v1 = c[im][in][rh*2+1] + __ldg(&bias[col+1]);
                if (G1){
                    v0 = cvt_rna_f(gelu_exact(v0));
                    v1 = cvt_rna_f(gelu_exact(v1));
                }
                *reinterpret_cast<float2*>(&Out[((size_t)e*MTOK + row)*Nout + col]) =
                    make_float2(v0, v1);
            }
        }
    }
}

// ---------------- host ----------------
extern "C" void kernel_launch(void* const* d_in, const int* in_sizes, int n_in,
                              void* d_out, int out_size)
{
    const float* x  = (const float*)d_in[0];   // [E, 2048, 1024]
    const float* w1 = (const float*)d_in[1];   // [E, 1024, 4096]
    const float* w2 = (const float*)d_in[2];   // [E, 4096, 1024]
    const float* b1 = (const float*)d_in[3];   // [4096]
    const float* b2 = (const float*)d_in[4];   // [1024]
    float* out = (float*)d_out;                // [E, 2048, 1024]

    float *xp, *w1p, *w2p, *hid;
    cudaGetSymbolAddress((void**)&xp,  g_xp);
    cudaGetSymbolAddress((void**)&w1p, g_w1p);
    cudaGetSymbolAddress((void**)&w2p, g_w2p);
    cudaGetSymbolAddress((void**)&hid, g_hid);

    cudaFuncSetAttribute(gemm_t<true>,  cudaFuncAttributeMaxDynamicSharedMemorySize, SMEM_BYTES);
    cudaFuncSetAttribute(gemm_t<false>, cudaFuncAttributeMaxDynamicSharedMemorySize, SMEM_BYTES);

    // pre-pass: rounding + weight transpose/pack (moves all cvt off the GEMM critical path)
    convert_x<<<4096, 256>>>((const float4*)x, (float4*)xp);
    pack_w<<<dim3(HID/128, DIM/32, EXPERTS), 256>>>(w1, w1p, DIM, HID);
    pack_w<<<dim3(DIM/128, HID/32, EXPERTS), 256>>>(w2, w2p, HID, DIM);

    // GEMM1 + exact GELU (rounds hidden for GEMM2)
    gemm_t<true><<<dim3(HID/BN, MTOK/BM, EXPERTS), 256, SMEM_BYTES>>>(xp, w1p, b1, hid, DIM);
    // GEMM2
    gemm_t<false><<<dim3(DIM/BN, MTOK/BM, EXPERTS), 256, SMEM_BYTES>>>(hid, w2p, b2, out, HID);
}